// round 2
// baseline (speedup 1.0000x reference)
#include <cuda_runtime.h>

#define N_NODES 262144
#define N_EDGES 2097152
#define GRIDW 8
#define NCLUS 64
#define EPSBN 1e-5f
#define ENC_NEGINF 0x007FFFFFu

// ---------------- static device scratch (no runtime allocation) ----------------
__device__ unsigned d_count[N_NODES];
__device__ unsigned d_excl[N_NODES];
__device__ unsigned d_offset[N_NODES];
__device__ unsigned d_cursor[N_NODES];
__device__ unsigned d_blockSum[256];
__device__ unsigned d_blockOff[256];
__device__ int      d_sorted_src[N_EDGES];
__device__ float4   d_g1v[N_NODES * 4];   // g1 = x*W1_row0 + b1          [N,16]
__device__ float4   d_g2v[N_NODES * 8];   // g2 = W2[0:16]^T h1 + b2      [N,32]
__device__ float4   d_h2v[N_NODES * 8];   // h2                            [N,32]
__device__ unsigned d_cnt64[NCLUS];
__device__ unsigned d_cur64[NCLUS];
__device__ int      d_perm[N_NODES];      // nodes grouped by cluster
__device__ unsigned char d_clus[N_NODES];
__device__ unsigned d_pool[NCLUS * 32];   // encoded-float max
__device__ int      d_is64;               // edge_index dtype flag

// monotone uint encoding of float (order-preserving)
__device__ __forceinline__ unsigned fenc(float f) {
    unsigned u = __float_as_uint(f);
    return (u & 0x80000000u) ? ~u : (u | 0x80000000u);
}
__device__ __forceinline__ float fdec(unsigned u) {
    return __uint_as_float((u & 0x80000000u) ? (u & 0x7FFFFFFFu) : ~u);
}

__device__ __forceinline__ unsigned warp_iscan(unsigned v, int lane) {
#pragma unroll
    for (int d = 1; d < 32; d <<= 1) {
        unsigned n = __shfl_up_sync(0xffffffffu, v, d);
        if (lane >= d) v += n;
    }
    return v;
}

// fetch edge endpoint under either dtype interpretation
__device__ __forceinline__ int edge_at(const void* ei, int is64, long long idx) {
    if (is64) return (int)((const long long*)ei)[idx];
    return ((const int*)ei)[idx];
}

// ---------------- K-1: detect edge_index dtype (int32 vs int64) --------------
__global__ void k_detect(const void* __restrict__ ei) {
    if (threadIdx.x == 0 && blockIdx.x == 0) {
        const int* p = (const int*)ei;
        int all_hi_zero = 1;
#pragma unroll
        for (int k = 0; k < 64; k++) {
            if (p[2 * k + 1] != 0) all_hi_zero = 0;
        }
        d_is64 = all_hi_zero;
    }
}

// ---------------- K0: zero tiny globals that receive cross-block atomics ------
__global__ void k_zero() {
    int t = blockIdx.x * blockDim.x + threadIdx.x;
    if (t < NCLUS * 32) d_pool[t] = ENC_NEGINF;
    if (t < NCLUS) d_cnt64[t] = 0u;
}

// ---------------- K1: per-node init: count=0, g1, cluster id + hist -----------
__global__ void __launch_bounds__(256) k_init(
    const float* __restrict__ x, const float* __restrict__ pos,
    const float* __restrict__ W1, const float* __restrict__ b1)
{
    __shared__ unsigned s_h[NCLUS];
    int t = threadIdx.x;
    if (t < NCLUS) s_h[t] = 0u;
    __syncthreads();

    int i = blockIdx.x * blockDim.x + t;   // grid exactly covers N
    d_count[i] = 0u;
    float xv = x[i];
    const float4* w0 = (const float4*)W1;  // row 0 of (4,16)
    const float4* bb = (const float4*)b1;
#pragma unroll
    for (int q = 0; q < 4; q++) {
        float4 w = w0[q], b = bb[q], g;
        g.x = fmaf(xv, w.x, b.x); g.y = fmaf(xv, w.y, b.y);
        g.z = fmaf(xv, w.z, b.z); g.w = fmaf(xv, w.w, b.w);
        d_g1v[i * 4 + q] = g;
    }
    float px = pos[3 * i], py = pos[3 * i + 1];
    int gx = (int)floorf(px * 0.0625f);
    int gy = (int)floorf(py * 0.0625f);
    int cl = gx + gy * GRIDW;
    cl = min(max(cl, 0), NCLUS - 1);
    d_clus[i] = (unsigned char)cl;
    atomicAdd(&s_h[cl], 1u);
    __syncthreads();
    if (t < NCLUS) atomicAdd(&d_cnt64[t], s_h[t]);
}

// ---------------- K2: edge histogram over dst ---------------------------------
__global__ void k_hist(const void* __restrict__ ei) {
    int e = blockIdx.x * blockDim.x + threadIdx.x;
    int is64 = d_is64;
    if (e < N_EDGES) {
        int dst = edge_at(ei, is64, (long long)N_EDGES + e);
        dst = min(max(dst, 0), N_NODES - 1);
        atomicAdd(&d_count[dst], 1u);
    }
}

// ---------------- K3/K4/K5: exclusive scan of d_count -------------------------
__global__ void __launch_bounds__(1024) k_scanA() {
    int t = threadIdx.x, b = blockIdx.x;
    int lane = t & 31, warp = t >> 5;
    int i = b * 1024 + t;
    unsigned v = d_count[i];
    unsigned incl = warp_iscan(v, lane);
    __shared__ unsigned sw[32];
    if (lane == 31) sw[warp] = incl;
    __syncthreads();
    if (warp == 0) {
        unsigned w = sw[lane];
        unsigned wi = warp_iscan(w, lane);
        sw[lane] = wi - w;  // exclusive
    }
    __syncthreads();
    unsigned excl = incl - v + sw[warp];
    d_excl[i] = excl;
    if (t == 1023) d_blockSum[b] = excl + v;
}

__global__ void k_scanB() {
    int t = threadIdx.x;  // 256 threads
    int lane = t & 31, warp = t >> 5;
    unsigned v = d_blockSum[t];
    unsigned incl = warp_iscan(v, lane);
    __shared__ unsigned sw[8];
    if (lane == 31) sw[warp] = incl;
    __syncthreads();
    if (warp == 0 && lane < 8) {
        unsigned w = sw[lane];
        unsigned wi = w;
#pragma unroll
        for (int d = 1; d < 8; d <<= 1) {
            unsigned n = __shfl_up_sync(0xffu, wi, d);
            if (lane >= d) wi += n;
        }
        sw[lane] = wi - w;
    }
    __syncthreads();
    d_blockOff[t] = incl - v + sw[warp];
    if (t == 0) {  // scan cluster counts -> cluster cursors
        unsigned run = 0;
        for (int c = 0; c < NCLUS; c++) {
            unsigned cv = d_cnt64[c];
            d_cur64[c] = run;
            run += cv;
        }
    }
}

__global__ void __launch_bounds__(1024) k_scanC() {
    int i = blockIdx.x * 1024 + threadIdx.x;
    unsigned o = d_excl[i] + d_blockOff[blockIdx.x];
    d_offset[i] = o;
    d_cursor[i] = o;
}

// ---------------- K6: scatter edges into CSR; also bin nodes by cluster -------
__global__ void k_scatter(const void* __restrict__ ei) {
    int e = blockIdx.x * blockDim.x + threadIdx.x;
    int is64 = d_is64;
    if (e < N_EDGES) {
        int src = edge_at(ei, is64, e);
        int dst = edge_at(ei, is64, (long long)N_EDGES + e);
        src = min(max(src, 0), N_NODES - 1);
        dst = min(max(dst, 0), N_NODES - 1);
        unsigned p = atomicAdd(&d_cursor[dst], 1u);
        d_sorted_src[p] = src;
    }
    if (e < N_NODES) {
        int cl = d_clus[e];
        unsigned p2 = atomicAdd(&d_cur64[cl], 1u);
        d_perm[p2] = e;
    }
}

// ---------------- K7: layer1 gather-max + BN + ReLU + fused g2 precompute -----
__global__ void __launch_bounds__(256) k_layer1(
    const float* __restrict__ pos,
    const float* __restrict__ W1,
    const float* __restrict__ bn1m, const float* __restrict__ bn1v,
    const float* __restrict__ bn1w, const float* __restrict__ bn1b,
    const float* __restrict__ W2,   const float* __restrict__ b2)
{
    __shared__ float s_w1[48];        // W1 rows 1..3
    __shared__ float s_a[16], s_b[16];
    __shared__ float s_W2[16 * 32];   // W2 rows 0..15
    __shared__ float s_b2[32];
    int t = threadIdx.x;
    if (t < 48) s_w1[t] = W1[16 + t];
    if (t < 16) {
        float sc = bn1w[t] * rsqrtf(bn1v[t] + EPSBN);
        s_a[t] = sc;
        s_b[t] = bn1b[t] - bn1m[t] * sc;
    }
    for (int k = t; k < 512; k += 256) s_W2[k] = W2[k];
    if (t < 32) s_b2[t] = b2[t];
    __syncthreads();

    int i = blockIdx.x * blockDim.x + t;
    float w1x[16], w1y[16], w1z[16];
#pragma unroll
    for (int c = 0; c < 16; c++) {
        w1x[c] = s_w1[c]; w1y[c] = s_w1[16 + c]; w1z[c] = s_w1[32 + c];
    }
    float pix = pos[3 * i], piy = pos[3 * i + 1], piz = pos[3 * i + 2];
    unsigned start = d_offset[i], deg = d_count[i];
    const float NEGINF = __int_as_float(0xff800000);
    float acc[16];
#pragma unroll
    for (int c = 0; c < 16; c++) acc[c] = NEGINF;

    for (unsigned e = 0; e < deg; e++) {
        int s = d_sorted_src[start + e];
        const float4* gp = &d_g1v[s * 4];
        float rx = pos[3 * s] - pix;
        float ry = pos[3 * s + 1] - piy;
        float rz = pos[3 * s + 2] - piz;
#pragma unroll
        for (int q = 0; q < 4; q++) {
            float4 a = gp[q];
            int c0 = q * 4;
            acc[c0 + 0] = fmaxf(acc[c0 + 0], a.x + rx * w1x[c0 + 0] + ry * w1y[c0 + 0] + rz * w1z[c0 + 0]);
            acc[c0 + 1] = fmaxf(acc[c0 + 1], a.y + rx * w1x[c0 + 1] + ry * w1y[c0 + 1] + rz * w1z[c0 + 1]);
            acc[c0 + 2] = fmaxf(acc[c0 + 2], a.z + rx * w1x[c0 + 2] + ry * w1y[c0 + 2] + rz * w1z[c0 + 2]);
            acc[c0 + 3] = fmaxf(acc[c0 + 3], a.w + rx * w1x[c0 + 3] + ry * w1y[c0 + 3] + rz * w1z[c0 + 3]);
        }
    }
    float h[16];
#pragma unroll
    for (int c = 0; c < 16; c++) {
        float agg = (deg == 0u) ? 0.0f : acc[c];
        h[c] = fmaxf(fmaf(agg, s_a[c], s_b[c]), 0.0f);
    }
    // g2 = W2a^T h + b2
    float g2a[32];
#pragma unroll
    for (int c = 0; c < 32; c++) g2a[c] = s_b2[c];
#pragma unroll
    for (int k = 0; k < 16; k++) {
        float hk = h[k];
#pragma unroll
        for (int c = 0; c < 32; c++) g2a[c] = fmaf(hk, s_W2[k * 32 + c], g2a[c]);
    }
    float4* op = &d_g2v[i * 8];
#pragma unroll
    for (int q = 0; q < 8; q++) {
        float4 o;
        o.x = g2a[4 * q]; o.y = g2a[4 * q + 1]; o.z = g2a[4 * q + 2]; o.w = g2a[4 * q + 3];
        op[q] = o;
    }
}

// ---------------- K8: layer2 gather-max + BN + ReLU -> h2 ---------------------
__global__ void __launch_bounds__(256) k_layer2(
    const float* __restrict__ pos,
    const float* __restrict__ W2,
    const float* __restrict__ bn2m, const float* __restrict__ bn2v,
    const float* __restrict__ bn2w, const float* __restrict__ bn2b)
{
    __shared__ float4 s_wx[8], s_wy[8], s_wz[8];   // W2 rows 16..18
    __shared__ float s_a[32], s_b[32];
    int t = threadIdx.x;
    if (t < 32) {
        ((float*)s_wx)[t] = W2[16 * 32 + t];
        ((float*)s_wy)[t] = W2[17 * 32 + t];
        ((float*)s_wz)[t] = W2[18 * 32 + t];
        float sc = bn2w[t] * rsqrtf(bn2v[t] + EPSBN);
        s_a[t] = sc;
        s_b[t] = bn2b[t] - bn2m[t] * sc;
    }
    __syncthreads();

    int i = blockIdx.x * blockDim.x + t;
    float pix = pos[3 * i], piy = pos[3 * i + 1], piz = pos[3 * i + 2];
    unsigned start = d_offset[i], deg = d_count[i];
    const float NEGINF = __int_as_float(0xff800000);
    float acc[32];
#pragma unroll
    for (int c = 0; c < 32; c++) acc[c] = NEGINF;

    for (unsigned e = 0; e < deg; e++) {
        int s = d_sorted_src[start + e];
        const float4* gp = &d_g2v[s * 8];
        float rx = pos[3 * s] - pix;
        float ry = pos[3 * s + 1] - piy;
        float rz = pos[3 * s + 2] - piz;
#pragma unroll
        for (int q = 0; q < 8; q++) {
            float4 g = gp[q];
            float4 wx = s_wx[q], wy = s_wy[q], wz = s_wz[q];
            int c0 = q * 4;
            acc[c0 + 0] = fmaxf(acc[c0 + 0], g.x + rx * wx.x + ry * wy.x + rz * wz.x);
            acc[c0 + 1] = fmaxf(acc[c0 + 1], g.y + rx * wx.y + ry * wy.y + rz * wz.y);
            acc[c0 + 2] = fmaxf(acc[c0 + 2], g.z + rx * wx.z + ry * wy.z + rz * wz.z);
            acc[c0 + 3] = fmaxf(acc[c0 + 3], g.w + rx * wx.w + ry * wy.w + rz * wz.w);
        }
    }
    float4* op = &d_h2v[i * 8];
#pragma unroll
    for (int q = 0; q < 8; q++) {
        float4 o;
        int c0 = q * 4;
        float a0 = (deg == 0u) ? 0.0f : acc[c0 + 0];
        float a1 = (deg == 0u) ? 0.0f : acc[c0 + 1];
        float a2 = (deg == 0u) ? 0.0f : acc[c0 + 2];
        float a3 = (deg == 0u) ? 0.0f : acc[c0 + 3];
        o.x = fmaxf(fmaf(a0, s_a[c0 + 0], s_b[c0 + 0]), 0.0f);
        o.y = fmaxf(fmaf(a1, s_a[c0 + 1], s_b[c0 + 1]), 0.0f);
        o.z = fmaxf(fmaf(a2, s_a[c0 + 2], s_b[c0 + 2]), 0.0f);
        o.w = fmaxf(fmaf(a3, s_a[c0 + 3], s_b[c0 + 3]), 0.0f);
        op[q] = o;
    }
}

// ---------------- K9: voxel max-pool via cluster-binned warp reduction --------
__global__ void __launch_bounds__(256) k_pool() {
    int t = blockIdx.x * blockDim.x + threadIdx.x;
    int lane = t & 31;
    int i = d_perm[t];
    int cl = d_clus[i];
    float h[32];
    const float4* hp = &d_h2v[i * 8];
#pragma unroll
    for (int q = 0; q < 8; q++) {
        float4 v = hp[q];
        h[4 * q] = v.x; h[4 * q + 1] = v.y; h[4 * q + 2] = v.z; h[4 * q + 3] = v.w;
    }
    int cl0 = __shfl_sync(0xffffffffu, cl, 0);
    bool uni = __all_sync(0xffffffffu, cl == cl0);
    if (uni) {
        float r = 0.0f;
#pragma unroll
        for (int c = 0; c < 32; c++) {
            float v = h[c];
#pragma unroll
            for (int d = 16; d; d >>= 1) v = fmaxf(v, __shfl_xor_sync(0xffffffffu, v, d));
            if (lane == c) r = v;
        }
        atomicMax(&d_pool[cl0 * 32 + lane], fenc(r));
    } else {
#pragma unroll
        for (int c = 0; c < 32; c++) atomicMax(&d_pool[cl * 32 + c], fenc(h[c]));
    }
}

// ---------------- K10: decode pooled -> output --------------------------------
__global__ void k_out(float* __restrict__ out) {
    int t = blockIdx.x * blockDim.x + threadIdx.x;
    if (t < NCLUS * 32) {
        unsigned u = d_pool[t];
        out[t] = (u == ENC_NEGINF) ? 0.0f : fdec(u);
    }
}

// ---------------- host launch -------------------------------------------------
extern "C" void kernel_launch(void* const* d_in, const int* in_sizes, int n_in,
                              void* d_out, int out_size)
{
    const float* x      = (const float*)d_in[0];
    const float* pos    = (const float*)d_in[1];
    const void*  ei     = (const void*)d_in[2];
    const float* W1     = (const float*)d_in[3];
    const float* b1     = (const float*)d_in[4];
    const float* bn1m   = (const float*)d_in[5];
    const float* bn1v   = (const float*)d_in[6];
    const float* bn1w   = (const float*)d_in[7];
    const float* bn1b   = (const float*)d_in[8];
    const float* W2     = (const float*)d_in[9];
    const float* b2     = (const float*)d_in[10];
    const float* bn2m   = (const float*)d_in[11];
    const float* bn2v   = (const float*)d_in[12];
    const float* bn2w   = (const float*)d_in[13];
    const float* bn2b   = (const float*)d_in[14];
    float* out = (float*)d_out;

    k_detect<<<1, 32>>>(ei);
    k_zero<<<8, 256>>>();
    k_init<<<N_NODES / 256, 256>>>(x, pos, W1, b1);
    k_hist<<<N_EDGES / 256, 256>>>(ei);
    k_scanA<<<256, 1024>>>();
    k_scanB<<<1, 256>>>();
    k_scanC<<<256, 1024>>>();
    k_scatter<<<N_EDGES / 256, 256>>>(ei);
    k_layer1<<<N_NODES / 256, 256>>>(pos, W1, bn1m, bn1v, bn1w, bn1b, W2, b2);
    k_layer2<<<N_NODES / 256, 256>>>(pos, W2, bn2m, bn2v, bn2w, bn2b);
    k_pool<<<N_NODES / 256, 256>>>();
    k_out<<<8, 256>>>(out);
}

// round 3
// speedup vs baseline: 1.4467x; 1.4467x over previous
#include <cuda_runtime.h>

#define N_NODES 262144
#define N_EDGES 2097152
#define GRIDW 8
#define NCLUS 64
#define EPSBN 1e-5f

// ---------------- static device scratch ----------------
__device__ unsigned d_count[N_NODES];
__device__ unsigned d_excl[N_NODES];
__device__ unsigned d_offset[N_NODES];
__device__ unsigned d_cursor[N_NODES];
__device__ unsigned d_blockSum[256];
__device__ unsigned d_blockOff[256];
__device__ int      d_sorted_src[N_EDGES];
__device__ float4   d_G1[N_NODES * 4];   // G1 = x*W1_0 + b1 + pos*W1_pos   [N,16]
__device__ float4   d_G2[N_NODES * 8];   // G2 = W2a^T h1 + b2 + pos*W2_pos [N,32]
__device__ unsigned char d_clus[N_NODES];
__device__ unsigned d_pool[NCLUS * 32];  // encoded nonneg-float max (0 = empty)
__device__ int      d_is64;

__device__ __forceinline__ unsigned warp_iscan(unsigned v, int lane) {
#pragma unroll
    for (int d = 1; d < 32; d <<= 1) {
        unsigned n = __shfl_up_sync(0xffffffffu, v, d);
        if (lane >= d) v += n;
    }
    return v;
}

__device__ __forceinline__ int edge_at(const void* ei, int is64, long long idx) {
    if (is64) return (int)((const long long*)ei)[idx];
    return ((const int*)ei)[idx];
}

// ---------------- K0: zero pool + detect edge dtype ---------------------------
__global__ void k_zero(const void* __restrict__ ei) {
    int t = blockIdx.x * blockDim.x + threadIdx.x;
    if (t < NCLUS * 32) d_pool[t] = 0u;
    if (t == 0) {
        const int* p = (const int*)ei;
        int all_hi_zero = 1;
#pragma unroll
        for (int k = 0; k < 64; k++)
            if (p[2 * k + 1] != 0) all_hi_zero = 0;
        d_is64 = all_hi_zero;
    }
}

// ---------------- K1: per-node init: count=0, G1, cluster id ------------------
__global__ void __launch_bounds__(256) k_init(
    const float* __restrict__ x, const float* __restrict__ pos,
    const float* __restrict__ W1, const float* __restrict__ b1)
{
    int t = threadIdx.x;
    int i = blockIdx.x * blockDim.x + t;   // grid exactly covers N
    d_count[i] = 0u;
    float xv = x[i];
    float px = pos[3 * i], py = pos[3 * i + 1], pz = pos[3 * i + 2];
#pragma unroll
    for (int q = 0; q < 4; q++) {
        float4 g;
        float* gv = (float*)&g;
#pragma unroll
        for (int j = 0; j < 4; j++) {
            int c = q * 4 + j;
            float v = b1[c];
            v = fmaf(xv, W1[c],      v);
            v = fmaf(px, W1[16 + c], v);
            v = fmaf(py, W1[32 + c], v);
            v = fmaf(pz, W1[48 + c], v);
            gv[j] = v;
        }
        d_G1[i * 4 + q] = g;
    }
    int gx = (int)floorf(px * 0.0625f);
    int gy = (int)floorf(py * 0.0625f);
    int cl = gx + gy * GRIDW;
    d_clus[i] = (unsigned char)min(max(cl, 0), NCLUS - 1);
}

// ---------------- K2: edge histogram over dst ---------------------------------
__global__ void k_hist(const void* __restrict__ ei) {
    int e = blockIdx.x * blockDim.x + threadIdx.x;
    int is64 = d_is64;
    if (e < N_EDGES) {
        int dst = edge_at(ei, is64, (long long)N_EDGES + e);
        dst = min(max(dst, 0), N_NODES - 1);
        atomicAdd(&d_count[dst], 1u);
    }
}

// ---------------- K3/K4/K5: exclusive scan of d_count -------------------------
__global__ void __launch_bounds__(1024) k_scanA() {
    int t = threadIdx.x, b = blockIdx.x;
    int lane = t & 31, warp = t >> 5;
    int i = b * 1024 + t;
    unsigned v = d_count[i];
    unsigned incl = warp_iscan(v, lane);
    __shared__ unsigned sw[32];
    if (lane == 31) sw[warp] = incl;
    __syncthreads();
    if (warp == 0) {
        unsigned w = sw[lane];
        unsigned wi = warp_iscan(w, lane);
        sw[lane] = wi - w;
    }
    __syncthreads();
    unsigned excl = incl - v + sw[warp];
    d_excl[i] = excl;
    if (t == 1023) d_blockSum[b] = excl + v;
}

__global__ void k_scanB() {
    int t = threadIdx.x;  // 256 threads
    int lane = t & 31, warp = t >> 5;
    unsigned v = d_blockSum[t];
    unsigned incl = warp_iscan(v, lane);
    __shared__ unsigned sw[8];
    if (lane == 31) sw[warp] = incl;
    __syncthreads();
    if (warp == 0 && lane < 8) {
        unsigned w = sw[lane];
        unsigned wi = w;
#pragma unroll
        for (int d = 1; d < 8; d <<= 1) {
            unsigned n = __shfl_up_sync(0xffu, wi, d);
            if (lane >= d) wi += n;
        }
        sw[lane] = wi - w;
    }
    __syncthreads();
    d_blockOff[t] = incl - v + sw[warp];
}

__global__ void __launch_bounds__(1024) k_scanC() {
    int i = blockIdx.x * 1024 + threadIdx.x;
    unsigned o = d_excl[i] + d_blockOff[blockIdx.x];
    d_offset[i] = o;
    d_cursor[i] = o;
}

// ---------------- K6: scatter edges into CSR ----------------------------------
__global__ void k_scatter(const void* __restrict__ ei) {
    int e = blockIdx.x * blockDim.x + threadIdx.x;
    int is64 = d_is64;
    if (e < N_EDGES) {
        int src = edge_at(ei, is64, e);
        int dst = edge_at(ei, is64, (long long)N_EDGES + e);
        src = min(max(src, 0), N_NODES - 1);
        dst = min(max(dst, 0), N_NODES - 1);
        unsigned p = atomicAdd(&d_cursor[dst], 1u);
        d_sorted_src[p] = src;
    }
}

// ---------------- K7: layer1 seg-max of G1, BN+ReLU, emit G2 ------------------
__global__ void __launch_bounds__(256) k_layer1(
    const float* __restrict__ pos,
    const float* __restrict__ W1,
    const float* __restrict__ bn1m, const float* __restrict__ bn1v,
    const float* __restrict__ bn1w, const float* __restrict__ bn1b,
    const float* __restrict__ W2,   const float* __restrict__ b2)
{
    __shared__ float s_w1p[48];       // W1 rows 1..3 (pos part), [3][16]
    __shared__ float s_a[16], s_b[16];
    __shared__ float s_W2a[16 * 32];  // W2 rows 0..15
    __shared__ float s_W2p[96];       // W2 rows 16..18, [3][32]
    __shared__ float s_b2[32];
    int t = threadIdx.x;
    if (t < 48) s_w1p[t] = W1[16 + t];
    if (t < 16) {
        float sc = bn1w[t] * rsqrtf(bn1v[t] + EPSBN);
        s_a[t] = sc;
        s_b[t] = bn1b[t] - bn1m[t] * sc;
    }
    for (int k = t; k < 512; k += 256) s_W2a[k] = W2[k];
    if (t < 96) s_W2p[t] = W2[16 * 32 + t];
    if (t < 32) s_b2[t] = b2[t];
    __syncthreads();

    int i = blockIdx.x * blockDim.x + t;
    unsigned start = d_offset[i], deg = d_count[i];
    const float NEGINF = __int_as_float(0xff800000);
    float4 a0 = {NEGINF, NEGINF, NEGINF, NEGINF};
    float4 a1 = a0, a2 = a0, a3 = a0;

#pragma unroll 2
    for (unsigned e = 0; e < deg; e++) {
        int s = d_sorted_src[start + e];
        const float4* gp = &d_G1[s * 4];
        float4 g0 = gp[0], g1 = gp[1], g2 = gp[2], g3 = gp[3];
        a0.x = fmaxf(a0.x, g0.x); a0.y = fmaxf(a0.y, g0.y); a0.z = fmaxf(a0.z, g0.z); a0.w = fmaxf(a0.w, g0.w);
        a1.x = fmaxf(a1.x, g1.x); a1.y = fmaxf(a1.y, g1.y); a1.z = fmaxf(a1.z, g1.z); a1.w = fmaxf(a1.w, g1.w);
        a2.x = fmaxf(a2.x, g2.x); a2.y = fmaxf(a2.y, g2.y); a2.z = fmaxf(a2.z, g2.z); a2.w = fmaxf(a2.w, g2.w);
        a3.x = fmaxf(a3.x, g3.x); a3.y = fmaxf(a3.y, g3.y); a3.z = fmaxf(a3.z, g3.z); a3.w = fmaxf(a3.w, g3.w);
    }
    float acc[16];
    ((float4*)acc)[0] = a0; ((float4*)acc)[1] = a1;
    ((float4*)acc)[2] = a2; ((float4*)acc)[3] = a3;

    float px = pos[3 * i], py = pos[3 * i + 1], pz = pos[3 * i + 2];
    float h[16];
#pragma unroll
    for (int c = 0; c < 16; c++) {
        float dterm = px * s_w1p[c] + py * s_w1p[16 + c] + pz * s_w1p[32 + c];
        float agg = (deg == 0u) ? 0.0f : (acc[c] - dterm);
        h[c] = fmaxf(fmaf(agg, s_a[c], s_b[c]), 0.0f);
    }
    // G2 = W2a^T h + b2 + pos * W2pos
    float g2a[32];
#pragma unroll
    for (int c = 0; c < 32; c++) {
        float v = s_b2[c];
        v = fmaf(px, s_W2p[c],      v);
        v = fmaf(py, s_W2p[32 + c], v);
        v = fmaf(pz, s_W2p[64 + c], v);
        g2a[c] = v;
    }
#pragma unroll
    for (int k = 0; k < 16; k++) {
        float hk = h[k];
#pragma unroll
        for (int c = 0; c < 32; c++) g2a[c] = fmaf(hk, s_W2a[k * 32 + c], g2a[c]);
    }
    float4* op = &d_G2[i * 8];
#pragma unroll
    for (int q = 0; q < 8; q++) op[q] = ((float4*)g2a)[q];
}

// ---------------- K8: layer2 seg-max of G2, BN+ReLU, fused voxel pool ---------
__global__ void __launch_bounds__(256) k_layer2pool(
    const float* __restrict__ pos,
    const float* __restrict__ W2,
    const float* __restrict__ bn2m, const float* __restrict__ bn2v,
    const float* __restrict__ bn2w, const float* __restrict__ bn2b)
{
    __shared__ float s_w2p[96];   // W2 rows 16..18
    __shared__ float s_a[32], s_b[32];
    __shared__ unsigned s_pool[NCLUS * 32];
    int t = threadIdx.x;
    if (t < 96) s_w2p[t] = W2[16 * 32 + t];
    if (t < 32) {
        float sc = bn2w[t] * rsqrtf(bn2v[t] + EPSBN);
        s_a[t] = sc;
        s_b[t] = bn2b[t] - bn2m[t] * sc;
    }
#pragma unroll
    for (int q = 0; q < 8; q++) s_pool[q * 256 + t] = 0u;
    __syncthreads();

    int i = blockIdx.x * blockDim.x + t;
    unsigned start = d_offset[i], deg = d_count[i];
    const float NEGINF = __int_as_float(0xff800000);
    float4 a0 = {NEGINF, NEGINF, NEGINF, NEGINF};
    float4 a1 = a0, a2 = a0, a3 = a0, a4 = a0, a5 = a0, a6 = a0, a7 = a0;

#pragma unroll 2
    for (unsigned e = 0; e < deg; e++) {
        int s = d_sorted_src[start + e];
        const float4* gp = &d_G2[s * 8];
        float4 g0 = gp[0], g1 = gp[1], g2 = gp[2], g3 = gp[3];
        float4 g4 = gp[4], g5 = gp[5], g6 = gp[6], g7 = gp[7];
        a0.x = fmaxf(a0.x, g0.x); a0.y = fmaxf(a0.y, g0.y); a0.z = fmaxf(a0.z, g0.z); a0.w = fmaxf(a0.w, g0.w);
        a1.x = fmaxf(a1.x, g1.x); a1.y = fmaxf(a1.y, g1.y); a1.z = fmaxf(a1.z, g1.z); a1.w = fmaxf(a1.w, g1.w);
        a2.x = fmaxf(a2.x, g2.x); a2.y = fmaxf(a2.y, g2.y); a2.z = fmaxf(a2.z, g2.z); a2.w = fmaxf(a2.w, g2.w);
        a3.x = fmaxf(a3.x, g3.x); a3.y = fmaxf(a3.y, g3.y); a3.z = fmaxf(a3.z, g3.z); a3.w = fmaxf(a3.w, g3.w);
        a4.x = fmaxf(a4.x, g4.x); a4.y = fmaxf(a4.y, g4.y); a4.z = fmaxf(a4.z, g4.z); a4.w = fmaxf(a4.w, g4.w);
        a5.x = fmaxf(a5.x, g5.x); a5.y = fmaxf(a5.y, g5.y); a5.z = fmaxf(a5.z, g5.z); a5.w = fmaxf(a5.w, g5.w);
        a6.x = fmaxf(a6.x, g6.x); a6.y = fmaxf(a6.y, g6.y); a6.z = fmaxf(a6.z, g6.z); a6.w = fmaxf(a6.w, g6.w);
        a7.x = fmaxf(a7.x, g7.x); a7.y = fmaxf(a7.y, g7.y); a7.z = fmaxf(a7.z, g7.z); a7.w = fmaxf(a7.w, g7.w);
    }
    float acc[32];
    ((float4*)acc)[0] = a0; ((float4*)acc)[1] = a1; ((float4*)acc)[2] = a2; ((float4*)acc)[3] = a3;
    ((float4*)acc)[4] = a4; ((float4*)acc)[5] = a5; ((float4*)acc)[6] = a6; ((float4*)acc)[7] = a7;

    float px = pos[3 * i], py = pos[3 * i + 1], pz = pos[3 * i + 2];
    int cl = d_clus[i];
    unsigned base = (unsigned)cl * 32u;
#pragma unroll
    for (int c = 0; c < 32; c++) {
        float dterm = px * s_w2p[c] + py * s_w2p[32 + c] + pz * s_w2p[64 + c];
        float agg = (deg == 0u) ? 0.0f : (acc[c] - dterm);
        float h2 = fmaxf(fmaf(agg, s_a[c], s_b[c]), 0.0f);   // >= 0
        unsigned enc = __float_as_uint(h2) | 0x80000000u;     // monotone for nonneg
        atomicMax(&s_pool[base + c], enc);
    }
    __syncthreads();
#pragma unroll
    for (int q = 0; q < 8; q++) {
        int j = q * 256 + t;
        unsigned v = s_pool[j];
        if (v) atomicMax(&d_pool[j], v);
    }
}

// ---------------- K9: decode pooled -> output ---------------------------------
__global__ void k_out(float* __restrict__ out) {
    int t = blockIdx.x * blockDim.x + threadIdx.x;
    if (t < NCLUS * 32) {
        unsigned u = d_pool[t];
        out[t] = u ? __uint_as_float(u & 0x7FFFFFFFu) : 0.0f;
    }
}

// ---------------- host launch -------------------------------------------------
extern "C" void kernel_launch(void* const* d_in, const int* in_sizes, int n_in,
                              void* d_out, int out_size)
{
    const float* x    = (const float*)d_in[0];
    const float* pos  = (const float*)d_in[1];
    const void*  ei   = (const void*)d_in[2];
    const float* W1   = (const float*)d_in[3];
    const float* b1   = (const float*)d_in[4];
    const float* bn1m = (const float*)d_in[5];
    const float* bn1v = (const float*)d_in[6];
    const float* bn1w = (const float*)d_in[7];
    const float* bn1b = (const float*)d_in[8];
    const float* W2   = (const float*)d_in[9];
    const float* b2   = (const float*)d_in[10];
    const float* bn2m = (const float*)d_in[11];
    const float* bn2v = (const float*)d_in[12];
    const float* bn2w = (const float*)d_in[13];
    const float* bn2b = (const float*)d_in[14];
    float* out = (float*)d_out;

    k_zero<<<8, 256>>>(ei);
    k_init<<<N_NODES / 256, 256>>>(x, pos, W1, b1);
    k_hist<<<N_EDGES / 256, 256>>>(ei);
    k_scanA<<<256, 1024>>>();
    k_scanB<<<1, 256>>>();
    k_scanC<<<256, 1024>>>();
    k_scatter<<<N_EDGES / 256, 256>>>(ei);
    k_layer1<<<N_NODES / 256, 256>>>(pos, W1, bn1m, bn1v, bn1w, bn1b, W2, b2);
    k_layer2pool<<<N_NODES / 256, 256>>>(pos, W2, bn2m, bn2v, bn2w, bn2b);
    k_out<<<8, 256>>>(out);
}